// round 10
// baseline (speedup 1.0000x reference)
#include <cuda_runtime.h>
#include <cuda_bf16.h>
#include <cstdint>

// Problem constants
#define Bq 8
#define Fq 256
#define Tq 32
#define Dq 1024
#define NEGV (-1e30f)

// ---------------------------------------------------------------------------
// Device-global scratch (no allocation allowed)
// ---------------------------------------------------------------------------
__device__ float g_tpp[Bq * Tq * Dq];            // txt@Ws + b     (1 MB)
__device__ float g_fp [Bq * Fq * Dq];            // feat@W         (8 MB)

__device__ __nv_bfloat16 g_fh [Bq * Fq * Dq];    // feat hi
__device__ __nv_bfloat16 g_fl [Bq * Fq * Dq];    // feat lo
__device__ __nv_bfloat16 g_th [Bq * Tq * Dq];    // txt hi
__device__ __nv_bfloat16 g_tl [Bq * Tq * Dq];    // txt lo
__device__ __nv_bfloat16 g_wth[Dq * Dq];         // W^T hi  ([n][k])
__device__ __nv_bfloat16 g_wtl[Dq * Dq];         // W^T lo
__device__ __nv_bfloat16 g_wsh[Dq * Dq];         // Ws^T hi
__device__ __nv_bfloat16 g_wsl[Dq * Dq];         // Ws^T lo

// ---------------------------------------------------------------------------
// Helpers
// ---------------------------------------------------------------------------
__device__ __forceinline__ uint32_t smem_to_u32(const void* p) {
    uint32_t a;
    asm("{ .reg .u64 t; cvta.to.shared.u64 t, %1; cvt.u32.u64 %0, t; }"
        : "=r"(a) : "l"(p));
    return a;
}

__device__ __forceinline__ void mma_bf16(float* c, const uint32_t* a, const uint32_t* b) {
    asm volatile(
        "mma.sync.aligned.m16n8k16.row.col.f32.bf16.bf16.f32 "
        "{%0,%1,%2,%3}, {%4,%5,%6,%7}, {%8,%9}, {%0,%1,%2,%3};"
        : "+f"(c[0]), "+f"(c[1]), "+f"(c[2]), "+f"(c[3])
        : "r"(a[0]), "r"(a[1]), "r"(a[2]), "r"(a[3]), "r"(b[0]), "r"(b[1]));
}

#define LDSM_X4(r0, r1, r2, r3, addr)                                        \
    asm volatile("ldmatrix.sync.aligned.m8n8.x4.shared.b16 {%0,%1,%2,%3}, [%4];" \
                 : "=r"(r0), "=r"(r1), "=r"(r2), "=r"(r3) : "r"(addr))

__device__ __forceinline__ void cp16(uint32_t dst, const void* src) {
    asm volatile("cp.async.cg.shared.global [%0], [%1], 16;" :: "r"(dst), "l"(src));
}
#define CP_COMMIT() asm volatile("cp.async.commit_group;" ::: "memory")
#define CP_WAIT1()  asm volatile("cp.async.wait_group 1;" ::: "memory")
#define CP_WAIT0()  asm volatile("cp.async.wait_group 0;" ::: "memory")

// single-MUFU tanh
__device__ __forceinline__ float tanh_mufu(float x) {
    float y;
    asm("tanh.approx.f32 %0, %1;" : "=f"(y) : "f"(x));
    return y;
}
// 2-MUFU accurate tanh (for the per-block scalars; avoids libm blob)
__device__ __forceinline__ float ftanh_fast(float x) {
    float e = __expf(2.0f * x);
    return 1.0f - __fdividef(2.0f, e + 1.0f);
}

// ---------------------------------------------------------------------------
// Merged prep: activation hi/lo split + weight transpose/split in ONE launch.
// ---------------------------------------------------------------------------
#define FEAT4 (Bq * Fq * Dq / 4)
#define TXT4  (Bq * Tq * Dq / 4)
#define SPLIT_BLOCKS ((FEAT4 + TXT4 + 255) / 256)   // 2304
#define TRANS_BLOCKS (32 * 32 * 2)                  // 2048

__global__ void __launch_bounds__(256)
prep_kernel(const float* __restrict__ feat, __nv_bfloat16* __restrict__ fh,
            __nv_bfloat16* __restrict__ fl,
            const float* __restrict__ txt, __nv_bfloat16* __restrict__ th,
            __nv_bfloat16* __restrict__ tl,
            const float* __restrict__ W0, __nv_bfloat16* __restrict__ H0,
            __nv_bfloat16* __restrict__ L0,
            const float* __restrict__ W1, __nv_bfloat16* __restrict__ H1,
            __nv_bfloat16* __restrict__ L1) {
    __shared__ float ts[32][33];
    const int blk = blockIdx.x;
    const int tid = threadIdx.x;

    if (blk < SPLIT_BLOCKS) {
        int i = blk * 256 + tid;
        const float* in;
        __nv_bfloat16 *hi, *lo;
        if (i < FEAT4) {
            in = feat; hi = fh; lo = fl;
        } else if (i < FEAT4 + TXT4) {
            i -= FEAT4;
            in = txt; hi = th; lo = tl;
        } else {
            return;
        }
        float4 v = ((const float4*)in)[i];
        __nv_bfloat16 h0 = __float2bfloat16(v.x);
        __nv_bfloat16 h1 = __float2bfloat16(v.y);
        __nv_bfloat16 h2 = __float2bfloat16(v.z);
        __nv_bfloat16 h3 = __float2bfloat16(v.w);
        __nv_bfloat16 l0 = __float2bfloat16(v.x - __bfloat162float(h0));
        __nv_bfloat16 l1 = __float2bfloat16(v.y - __bfloat162float(h1));
        __nv_bfloat16 l2 = __float2bfloat16(v.z - __bfloat162float(h2));
        __nv_bfloat16 l3 = __float2bfloat16(v.w - __bfloat162float(h3));
        ((__nv_bfloat162*)hi)[2 * i]     = __nv_bfloat162(h0, h1);
        ((__nv_bfloat162*)hi)[2 * i + 1] = __nv_bfloat162(h2, h3);
        ((__nv_bfloat162*)lo)[2 * i]     = __nv_bfloat162(l0, l1);
        ((__nv_bfloat162*)lo)[2 * i + 1] = __nv_bfloat162(l2, l3);
    } else {
        const int idx   = blk - SPLIT_BLOCKS;
        const int which = idx >> 10;            // 0 -> W, 1 -> Ws
        const int tile  = idx & 1023;
        const int n0 = (tile & 31) * 32;
        const int k0 = (tile >> 5) * 32;
        const float* in = which ? W1 : W0;
        __nv_bfloat16* hi = which ? H1 : H0;
        __nv_bfloat16* lo = which ? L1 : L0;
        const int tx = tid & 31, ty = tid >> 5;  // (32, 8)
#pragma unroll
        for (int i = 0; i < 32; i += 8)
            ts[ty + i][tx] = in[(size_t)(k0 + ty + i) * Dq + n0 + tx];
        __syncthreads();
#pragma unroll
        for (int i = 0; i < 32; i += 8) {
            float v = ts[tx][ty + i];           // = W[k0+tx][n0+ty+i]
            __nv_bfloat16 h = __float2bfloat16(v);
            __nv_bfloat16 l = __float2bfloat16(v - __bfloat162float(h));
            size_t o = (size_t)(n0 + ty + i) * Dq + k0 + tx;
            hi[o] = h;
            lo[o] = l;
        }
    }
}

// ---------------------------------------------------------------------------
// bf16x3 emulated-fp32 GEMM on mma.sync (m16n8k16 bf16).
// CTA tile 128(m) x 64(n), BK=32, 2-stage cp.async pipeline, 2 CTAs/SM.
// ---------------------------------------------------------------------------
#define BK 32
#define NC (Dq / BK)                 // 32
#define ROWB 80                      // 32 bf16 = 64B + 16B pad (conflict-free)
#define ATILE (128 * ROWB)           // 10240
#define BTILE (64 * ROWB)            // 5120
#define OFF_AH 0
#define OFF_AL ATILE
#define OFF_BH (2 * ATILE)
#define OFF_BL (2 * ATILE + BTILE)
#define STAGEB (2 * ATILE + 2 * BTILE)   // 30720
#define SMEM_GEMM (2 * STAGEB)           // 61440

__device__ __forceinline__ void cp_tileA(uint32_t s, const __nv_bfloat16* __restrict__ g,
                                         int row0, int kc, int tid) {
#pragma unroll
    for (int i = 0; i < 2; i++) {
        int idx = tid + (i << 8);          // 0..511
        int r = idx >> 2, c = idx & 3;
        cp16(s + r * ROWB + c * 16, g + (size_t)(row0 + r) * Dq + kc + c * 8);
    }
}
__device__ __forceinline__ void cp_tileB(uint32_t s, const __nv_bfloat16* __restrict__ g,
                                         int row0, int kc, int tid) {
    int r = tid >> 2, c = tid & 3;         // 64 rows x 4 chunks
    cp16(s + r * ROWB + c * 16, g + (size_t)(row0 + r) * Dq + kc + c * 8);
}

__global__ void __launch_bounds__(256, 2)
mma_gemm_kernel(const __nv_bfloat16* __restrict__ A2h, const __nv_bfloat16* __restrict__ A2l,
                const __nv_bfloat16* __restrict__ B2h, const __nv_bfloat16* __restrict__ B2l,
                float* __restrict__ C2,
                const __nv_bfloat16* __restrict__ A1h, const __nv_bfloat16* __restrict__ A1l,
                const __nv_bfloat16* __restrict__ B1h, const __nv_bfloat16* __restrict__ B1l,
                float* __restrict__ C1, const float* __restrict__ bias1) {
    extern __shared__ char sm[];
    const uint32_t smb = smem_to_u32(sm);
    const int tid  = threadIdx.x;
    const int wid  = tid >> 5;
    const int lane = tid & 31;

    const bool st1 = (blockIdx.y >= 16);
    const int  m0  = st1 ? (int)(blockIdx.y - 16) * 128 : (int)blockIdx.y * 128;
    const int  n0  = blockIdx.x * 64;
    const __nv_bfloat16* Ah = st1 ? A1h : A2h;
    const __nv_bfloat16* Al = st1 ? A1l : A2l;
    const __nv_bfloat16* Bh = st1 ? B1h : B2h;
    const __nv_bfloat16* Bl = st1 ? B1l : B2l;
    float* C = st1 ? C1 : C2;

    const int wm = (wid >> 2) * 64;        // warp m offset
    const int wn = (wid & 3) * 16;         // warp n offset

    float acc[4][2][4];
#pragma unroll
    for (int i = 0; i < 4; i++)
#pragma unroll
        for (int j = 0; j < 2; j++)
#pragma unroll
            for (int k = 0; k < 4; k++) acc[i][j][k] = 0.0f;

    // prologue: chunk 0
    cp_tileA(smb + OFF_AH, Ah, m0, 0, tid);
    cp_tileA(smb + OFF_AL, Al, m0, 0, tid);
    cp_tileB(smb + OFF_BH, Bh, n0, 0, tid);
    cp_tileB(smb + OFF_BL, Bl, n0, 0, tid);
    CP_COMMIT();

    const int lg = lane >> 3;              // 0..3
    const int lr = lane & 7;

    for (int c = 0; c < NC; c++) {
        if (c + 1 < NC) {
            uint32_t base = smb + ((c + 1) & 1) * STAGEB;
            const int kc = (c + 1) * BK;
            cp_tileA(base + OFF_AH, Ah, m0, kc, tid);
            cp_tileA(base + OFF_AL, Al, m0, kc, tid);
            cp_tileB(base + OFF_BH, Bh, n0, kc, tid);
            cp_tileB(base + OFF_BL, Bl, n0, kc, tid);
            CP_COMMIT();
            CP_WAIT1();
        } else {
            CP_WAIT0();
        }
        __syncthreads();

        const uint32_t base = smb + (c & 1) * STAGEB;

#pragma unroll
        for (int ks = 0; ks < 2; ks++) {
            const int k0 = ks * 16;
            uint32_t bH[2][2], bL[2][2];
            const uint32_t b_off =
                (uint32_t)((wn + ((lg >> 1) << 3) + lr) * ROWB + (k0 + ((lg & 1) << 3)) * 2);
            LDSM_X4(bH[0][0], bH[0][1], bH[1][0], bH[1][1], base + OFF_BH + b_off);
            LDSM_X4(bL[0][0], bL[0][1], bL[1][0], bL[1][1], base + OFF_BL + b_off);

            const uint32_t a_off =
                (uint32_t)((wm + ((lg & 1) << 3) + lr) * ROWB + (k0 + ((lg >> 1) << 3)) * 2);
#pragma unroll
            for (int mt = 0; mt < 4; mt++) {
                uint32_t aH[4], aL[4];
                LDSM_X4(aH[0], aH[1], aH[2], aH[3],
                        base + OFF_AH + a_off + mt * 16 * ROWB);
                LDSM_X4(aL[0], aL[1], aL[2], aL[3],
                        base + OFF_AL + a_off + mt * 16 * ROWB);
#pragma unroll
                for (int nt = 0; nt < 2; nt++) {
                    mma_bf16(acc[mt][nt], aH, bH[nt]);
                    mma_bf16(acc[mt][nt], aH, bL[nt]);
                    mma_bf16(acc[mt][nt], aL, bH[nt]);
                }
            }
        }
        __syncthreads();
    }

    // Epilogue
    const int row_base = m0 + wm + (lane >> 2);
    const int col_base = n0 + wn + (lane & 3) * 2;
#pragma unroll
    for (int mt = 0; mt < 4; mt++) {
#pragma unroll
        for (int nt = 0; nt < 2; nt++) {
            const int r = row_base + mt * 16;
            const int cc = col_base + nt * 8;
            float2 v01 = make_float2(acc[mt][nt][0], acc[mt][nt][1]);
            float2 v23 = make_float2(acc[mt][nt][2], acc[mt][nt][3]);
            if (st1) {
                float b0 = __ldg(&bias1[cc]);
                float b1 = __ldg(&bias1[cc + 1]);
                v01.x += b0; v01.y += b1;
                v23.x += b0; v23.y += b1;
            }
            *(float2*)&C[(size_t)r * Dq + cc] = v01;
            *(float2*)&C[(size_t)(r + 8) * Dq + cc] = v23;
        }
    }
}

// ---------------------------------------------------------------------------
// Fused attention epilogue, 16 frames per block, grid 128 = single wave.
// ALL hot data staged in dynamic smem (fp 64KB + full tpp[b] 128KB + wv 4KB):
// the rho inner loop is pure LDS + MUFU — no global latency exposure.
// ---------------------------------------------------------------------------
#define FPB 16
#define SMEM_ATTN ((FPB * Dq + Tq * Dq + Dq) * 4)   // 200704 bytes

__global__ void __launch_bounds__(256)
attn_kernel(const float* __restrict__ feat,
            const float* __restrict__ txt,
            const int*   __restrict__ qmask,
            const float* __restrict__ wv,
            const float* __restrict__ Wcw, const float* __restrict__ bcw,
            const float* __restrict__ Wcb, const float* __restrict__ bcb,
            float* __restrict__ out) {
    extern __shared__ float ds[];
    float* fp_s  = ds;                        // [FPB * Dq]
    float* tpp_s = ds + FPB * Dq;             // [Tq * Dq]
    float* wv_s  = ds + (FPB + Tq) * Dq;      // [Dq]

    __shared__ float rho_s[FPB][Tq];
    __shared__ float red_s[2][FPB][8];
    __shared__ float scal_s[FPB][2];

    const int f0   = blockIdx.x * FPB;        // base bf index
    const int b    = f0 >> 8;                 // F = 256
    const int tid  = threadIdx.x;
    const int warp = tid >> 5;
    const int lane = tid & 31;

    // Bulk-stage fp rows, full tpp[b], and wv via cp.async.
    {
        const uint32_t s_fp  = smem_to_u32(fp_s);
        const uint32_t s_tp  = smem_to_u32(tpp_s);
        const uint32_t s_wv  = smem_to_u32(wv_s);
        const float* gfp  = g_fp  + (size_t)f0 * Dq;
        const float* gtpp = g_tpp + (size_t)b * Tq * Dq;
#pragma unroll
        for (int i = 0; i < FPB * Dq / 4 / 256; i++) {
            int idx = tid + i * 256;
            cp16(s_fp + idx * 16, gfp + idx * 4);
        }
#pragma unroll
        for (int i = 0; i < Tq * Dq / 4 / 256; i++) {
            int idx = tid + i * 256;
            cp16(s_tp + idx * 16, gtpp + idx * 4);
        }
        cp16(s_wv + tid * 16, wv + tid * 4);
        CP_COMMIT();
        CP_WAIT0();
    }
    __syncthreads();

    // rho[j][t] = sum_d tanh(fp[j][d] + tpp[t][d]) * w[d]
    // Each warp owns 4 t-rows; per t, 16 frame-accumulators live in regs.
#pragma unroll
    for (int tloc = 0; tloc < 4; tloc++) {
        const int t = warp * 4 + tloc;
        const float* tr = tpp_s + t * Dq;
        float a[FPB];
#pragma unroll
        for (int j = 0; j < FPB; j++) a[j] = 0.0f;
#pragma unroll 2
        for (int d = lane * 4; d < Dq; d += 128) {
            float4 tv = *(const float4*)&tr[d];
            float4 w4 = *(const float4*)&wv_s[d];
#pragma unroll
            for (int j = 0; j < FPB; j++) {
                float4 f4 = *(const float4*)&fp_s[j * Dq + d];
                a[j] += tanh_mufu(f4.x + tv.x) * w4.x + tanh_mufu(f4.y + tv.y) * w4.y
                      + tanh_mufu(f4.z + tv.z) * w4.z + tanh_mufu(f4.w + tv.w) * w4.w;
            }
        }
#pragma unroll
        for (int o = 16; o; o >>= 1)
#pragma unroll
            for (int j = 0; j < FPB; j++)
                a[j] += __shfl_xor_sync(0xffffffffu, a[j], o);
        if (lane == 0) {
            float m = (float)qmask[b * Tq + t];
            float msk = (1.0f - m) * NEGV;
#pragma unroll
            for (int j = 0; j < FPB; j++)
                rho_s[j][t] = a[j] + msk;
        }
    }
    __syncthreads();

    // softmax over T=32 (each warp: frames warp*2, warp*2+1)
#pragma unroll
    for (int jj = 0; jj < 2; jj++) {
        const int j = warp * 2 + jj;
        float v = rho_s[j][lane];
        float mx = v;
#pragma unroll
        for (int o = 16; o; o >>= 1)
            mx = fmaxf(mx, __shfl_xor_sync(0xffffffffu, mx, o));
        float e = __expf(v - mx);
        float s = e;
#pragma unroll
        for (int o = 16; o; o >>= 1)
            s += __shfl_xor_sync(0xffffffffu, s, o);
        rho_s[j][lane] = e / s;
    }
    __syncthreads();

    // txt_h[j] + two dot products
    const int d0 = tid * 4;
    float4 th[FPB];
#pragma unroll
    for (int j = 0; j < FPB; j++) th[j] = make_float4(0.f, 0.f, 0.f, 0.f);
    const float* tb = txt + (size_t)b * Tq * Dq + d0;
#pragma unroll 2
    for (int t = 0; t < Tq; t++) {
        float4 v = *(const float4*)(tb + (size_t)t * Dq);
#pragma unroll
        for (int j = 0; j < FPB; j++) {
            const float a = rho_s[j][t];
            th[j].x = fmaf(a, v.x, th[j].x);
            th[j].y = fmaf(a, v.y, th[j].y);
            th[j].z = fmaf(a, v.z, th[j].z);
            th[j].w = fmaf(a, v.w, th[j].w);
        }
    }
    float4 cw = *(const float4*)&Wcw[d0];
    float4 cb = *(const float4*)&Wcb[d0];
#pragma unroll
    for (int j = 0; j < FPB; j++) {
        float dw = th[j].x * cw.x + th[j].y * cw.y + th[j].z * cw.z + th[j].w * cw.w;
        float db = th[j].x * cb.x + th[j].y * cb.y + th[j].z * cb.z + th[j].w * cb.w;
#pragma unroll
        for (int o = 16; o; o >>= 1) {
            dw += __shfl_xor_sync(0xffffffffu, dw, o);
            db += __shfl_xor_sync(0xffffffffu, db, o);
        }
        if (lane == 0) {
            red_s[0][j][warp] = dw;
            red_s[1][j][warp] = db;
        }
    }
    __syncthreads();
    if (tid < FPB) {
        float sw = 0.f, sb = 0.f;
#pragma unroll
        for (int i = 0; i < 8; i++) {
            sw += red_s[0][tid][i];
            sb += red_s[1][tid][i];
        }
        scal_s[tid][0] = ftanh_fast(sw + bcw[0]);
        scal_s[tid][1] = ftanh_fast(sb + bcb[0]);
    }
    __syncthreads();

#pragma unroll
    for (int j = 0; j < FPB; j++) {
        const float ws = scal_s[j][0];
        const float bs = scal_s[j][1];
        float4 f = *(const float4*)&feat[(size_t)(f0 + j) * Dq + d0];
        float4 o4;
        o4.x = fmaf(ws, f.x, bs);
        o4.y = fmaf(ws, f.y, bs);
        o4.z = fmaf(ws, f.z, bs);
        o4.w = fmaf(ws, f.w, bs);
        *(float4*)&out[(size_t)(f0 + j) * Dq + d0] = o4;
    }
}

// ---------------------------------------------------------------------------
extern "C" void kernel_launch(void* const* d_in, const int* in_sizes, int n_in,
                              void* d_out, int out_size) {
    const float* features = (const float*)d_in[0];
    const float* txt      = (const float*)d_in[2];
    const int*   qm       = (const int*)  d_in[3];
    const float* Ws       = (const float*)d_in[4];
    const float* W        = (const float*)d_in[5];
    const float* wvec     = (const float*)d_in[6];
    const float* bvec     = (const float*)d_in[7];
    const float* Wcw      = (const float*)d_in[8];
    const float* bcw      = (const float*)d_in[9];
    const float* Wcb      = (const float*)d_in[10];
    const float* bcb      = (const float*)d_in[11];
    float* out = (float*)d_out;

    float *tpp_p, *fp_p;
    __nv_bfloat16 *fh, *fl, *th, *tl, *wth, *wtl, *wsh, *wsl;
    cudaGetSymbolAddress((void**)&tpp_p, g_tpp);
    cudaGetSymbolAddress((void**)&fp_p,  g_fp);
    cudaGetSymbolAddress((void**)&fh,  g_fh);
    cudaGetSymbolAddress((void**)&fl,  g_fl);
    cudaGetSymbolAddress((void**)&th,  g_th);
    cudaGetSymbolAddress((void**)&tl,  g_tl);
    cudaGetSymbolAddress((void**)&wth, g_wth);
    cudaGetSymbolAddress((void**)&wtl, g_wtl);
    cudaGetSymbolAddress((void**)&wsh, g_wsh);
    cudaGetSymbolAddress((void**)&wsl, g_wsl);

    cudaFuncSetAttribute(mma_gemm_kernel,
                         cudaFuncAttributeMaxDynamicSharedMemorySize, SMEM_GEMM);
    cudaFuncSetAttribute(attn_kernel,
                         cudaFuncAttributeMaxDynamicSharedMemorySize, SMEM_ATTN);

    // 1) merged prep: activation split + weight transpose/split (one launch)
    prep_kernel<<<SPLIT_BLOCKS + TRANS_BLOCKS, 256>>>(
        features, fh, fl, txt, th, tl,
        W, wth, wtl, Ws, wsh, wsl);

    // 2) merged mma.sync GEMM, 288 CTAs, 2 CTAs/SM
    mma_gemm_kernel<<<dim3(Dq / 64, 18), 256, SMEM_GEMM>>>(
        fh, fl, wth, wtl, fp_p,
        th, tl, wsh, wsl, tpp_p, bvec);

    // 3) fused attention + film epilogue (128 blocks, one wave, smem-staged)
    attn_kernel<<<Bq * Fq / FPB, 256, SMEM_ATTN>>>(features, txt, qm, wvec,
                                                   Wcw, bcw, Wcb, bcb, out);
}

// round 11
// speedup vs baseline: 1.0028x; 1.0028x over previous
#include <cuda_runtime.h>
#include <cuda_bf16.h>
#include <cstdint>

// Problem constants
#define Bq 8
#define Fq 256
#define Tq 32
#define Dq 1024
#define NEGV (-1e30f)

// ---------------------------------------------------------------------------
// Device-global scratch (no allocation allowed)
// ---------------------------------------------------------------------------
__device__ float g_tpp[Bq * Tq * Dq];            // txt@Ws + b     (1 MB)
__device__ float g_fp [Bq * Fq * Dq];            // feat@W         (8 MB)

__device__ __nv_bfloat16 g_fh [Bq * Fq * Dq];    // feat hi
__device__ __nv_bfloat16 g_fl [Bq * Fq * Dq];    // feat lo
__device__ __nv_bfloat16 g_th [Bq * Tq * Dq];    // txt hi
__device__ __nv_bfloat16 g_tl [Bq * Tq * Dq];    // txt lo
__device__ __nv_bfloat16 g_wth[Dq * Dq];         // W^T hi  ([n][k])
__device__ __nv_bfloat16 g_wtl[Dq * Dq];         // W^T lo
__device__ __nv_bfloat16 g_wsh[Dq * Dq];         // Ws^T hi
__device__ __nv_bfloat16 g_wsl[Dq * Dq];         // Ws^T lo

// ---------------------------------------------------------------------------
// Helpers
// ---------------------------------------------------------------------------
__device__ __forceinline__ uint32_t smem_to_u32(const void* p) {
    uint32_t a;
    asm("{ .reg .u64 t; cvta.to.shared.u64 t, %1; cvt.u32.u64 %0, t; }"
        : "=r"(a) : "l"(p));
    return a;
}

__device__ __forceinline__ void mma_bf16(float* c, const uint32_t* a, const uint32_t* b) {
    asm volatile(
        "mma.sync.aligned.m16n8k16.row.col.f32.bf16.bf16.f32 "
        "{%0,%1,%2,%3}, {%4,%5,%6,%7}, {%8,%9}, {%0,%1,%2,%3};"
        : "+f"(c[0]), "+f"(c[1]), "+f"(c[2]), "+f"(c[3])
        : "r"(a[0]), "r"(a[1]), "r"(a[2]), "r"(a[3]), "r"(b[0]), "r"(b[1]));
}

#define LDSM_X4(r0, r1, r2, r3, addr)                                        \
    asm volatile("ldmatrix.sync.aligned.m8n8.x4.shared.b16 {%0,%1,%2,%3}, [%4];" \
                 : "=r"(r0), "=r"(r1), "=r"(r2), "=r"(r3) : "r"(addr))

__device__ __forceinline__ void cp16(uint32_t dst, const void* src) {
    asm volatile("cp.async.cg.shared.global [%0], [%1], 16;" :: "r"(dst), "l"(src));
}
#define CP_COMMIT() asm volatile("cp.async.commit_group;" ::: "memory")
#define CP_WAIT1()  asm volatile("cp.async.wait_group 1;" ::: "memory")
#define CP_WAIT0()  asm volatile("cp.async.wait_group 0;" ::: "memory")

// ---------------------------------------------------------------------------
// Paired half-precision tanh: 2 elements per MUFU via tanh.approx.f16x2.
// Args computed/packed from fp32, result unpacked to fp32 (fp32 accumulation).
// ---------------------------------------------------------------------------
__device__ __forceinline__ float2 tanh2_f16(float x, float y) {
    uint32_t p, r;
    asm("{\n\t.reg .f16 h0, h1;\n\t"
        "cvt.rn.f16.f32 h0, %1;\n\t"
        "cvt.rn.f16.f32 h1, %2;\n\t"
        "mov.b32 %0, {h0, h1};\n\t}" : "=r"(p) : "f"(x), "f"(y));
    asm("tanh.approx.f16x2 %0, %1;" : "=r"(r) : "r"(p));
    float2 o;
    asm("{\n\t.reg .f16 h0, h1;\n\t"
        "mov.b32 {h0, h1}, %2;\n\t"
        "cvt.f32.f16 %0, h0;\n\t"
        "cvt.f32.f16 %1, h1;\n\t}" : "=f"(o.x), "=f"(o.y) : "r"(r));
    return o;
}

// 2-MUFU accurate tanh (for the per-block film scalars)
__device__ __forceinline__ float ftanh_fast(float x) {
    float e = __expf(2.0f * x);
    return 1.0f - __fdividef(2.0f, e + 1.0f);
}

// ---------------------------------------------------------------------------
// Merged prep: activation hi/lo split + weight transpose/split in ONE launch.
// ---------------------------------------------------------------------------
#define FEAT4 (Bq * Fq * Dq / 4)
#define TXT4  (Bq * Tq * Dq / 4)
#define SPLIT_BLOCKS ((FEAT4 + TXT4 + 255) / 256)   // 2304
#define TRANS_BLOCKS (32 * 32 * 2)                  // 2048

__global__ void __launch_bounds__(256)
prep_kernel(const float* __restrict__ feat, __nv_bfloat16* __restrict__ fh,
            __nv_bfloat16* __restrict__ fl,
            const float* __restrict__ txt, __nv_bfloat16* __restrict__ th,
            __nv_bfloat16* __restrict__ tl,
            const float* __restrict__ W0, __nv_bfloat16* __restrict__ H0,
            __nv_bfloat16* __restrict__ L0,
            const float* __restrict__ W1, __nv_bfloat16* __restrict__ H1,
            __nv_bfloat16* __restrict__ L1) {
    __shared__ float ts[32][33];
    const int blk = blockIdx.x;
    const int tid = threadIdx.x;

    if (blk < SPLIT_BLOCKS) {
        int i = blk * 256 + tid;
        const float* in;
        __nv_bfloat16 *hi, *lo;
        if (i < FEAT4) {
            in = feat; hi = fh; lo = fl;
        } else if (i < FEAT4 + TXT4) {
            i -= FEAT4;
            in = txt; hi = th; lo = tl;
        } else {
            return;
        }
        float4 v = ((const float4*)in)[i];
        __nv_bfloat16 h0 = __float2bfloat16(v.x);
        __nv_bfloat16 h1 = __float2bfloat16(v.y);
        __nv_bfloat16 h2 = __float2bfloat16(v.z);
        __nv_bfloat16 h3 = __float2bfloat16(v.w);
        __nv_bfloat16 l0 = __float2bfloat16(v.x - __bfloat162float(h0));
        __nv_bfloat16 l1 = __float2bfloat16(v.y - __bfloat162float(h1));
        __nv_bfloat16 l2 = __float2bfloat16(v.z - __bfloat162float(h2));
        __nv_bfloat16 l3 = __float2bfloat16(v.w - __bfloat162float(h3));
        ((__nv_bfloat162*)hi)[2 * i]     = __nv_bfloat162(h0, h1);
        ((__nv_bfloat162*)hi)[2 * i + 1] = __nv_bfloat162(h2, h3);
        ((__nv_bfloat162*)lo)[2 * i]     = __nv_bfloat162(l0, l1);
        ((__nv_bfloat162*)lo)[2 * i + 1] = __nv_bfloat162(l2, l3);
    } else {
        const int idx   = blk - SPLIT_BLOCKS;
        const int which = idx >> 10;            // 0 -> W, 1 -> Ws
        const int tile  = idx & 1023;
        const int n0 = (tile & 31) * 32;
        const int k0 = (tile >> 5) * 32;
        const float* in = which ? W1 : W0;
        __nv_bfloat16* hi = which ? H1 : H0;
        __nv_bfloat16* lo = which ? L1 : L0;
        const int tx = tid & 31, ty = tid >> 5;  // (32, 8)
#pragma unroll
        for (int i = 0; i < 32; i += 8)
            ts[ty + i][tx] = in[(size_t)(k0 + ty + i) * Dq + n0 + tx];
        __syncthreads();
#pragma unroll
        for (int i = 0; i < 32; i += 8) {
            float v = ts[tx][ty + i];           // = W[k0+tx][n0+ty+i]
            __nv_bfloat16 h = __float2bfloat16(v);
            __nv_bfloat16 l = __float2bfloat16(v - __bfloat162float(h));
            size_t o = (size_t)(n0 + ty + i) * Dq + k0 + tx;
            hi[o] = h;
            lo[o] = l;
        }
    }
}

// ---------------------------------------------------------------------------
// bf16x3 emulated-fp32 GEMM on mma.sync (m16n8k16 bf16).
// CTA tile 128(m) x 64(n), BK=32, 2-stage cp.async pipeline, 2 CTAs/SM.
// ---------------------------------------------------------------------------
#define BK 32
#define NC (Dq / BK)                 // 32
#define ROWB 80                      // 32 bf16 = 64B + 16B pad (conflict-free)
#define ATILE (128 * ROWB)           // 10240
#define BTILE (64 * ROWB)            // 5120
#define OFF_AH 0
#define OFF_AL ATILE
#define OFF_BH (2 * ATILE)
#define OFF_BL (2 * ATILE + BTILE)
#define STAGEB (2 * ATILE + 2 * BTILE)   // 30720
#define SMEM_GEMM (2 * STAGEB)           // 61440

__device__ __forceinline__ void cp_tileA(uint32_t s, const __nv_bfloat16* __restrict__ g,
                                         int row0, int kc, int tid) {
#pragma unroll
    for (int i = 0; i < 2; i++) {
        int idx = tid + (i << 8);          // 0..511
        int r = idx >> 2, c = idx & 3;
        cp16(s + r * ROWB + c * 16, g + (size_t)(row0 + r) * Dq + kc + c * 8);
    }
}
__device__ __forceinline__ void cp_tileB(uint32_t s, const __nv_bfloat16* __restrict__ g,
                                         int row0, int kc, int tid) {
    int r = tid >> 2, c = tid & 3;         // 64 rows x 4 chunks
    cp16(s + r * ROWB + c * 16, g + (size_t)(row0 + r) * Dq + kc + c * 8);
}

__global__ void __launch_bounds__(256, 2)
mma_gemm_kernel(const __nv_bfloat16* __restrict__ A2h, const __nv_bfloat16* __restrict__ A2l,
                const __nv_bfloat16* __restrict__ B2h, const __nv_bfloat16* __restrict__ B2l,
                float* __restrict__ C2,
                const __nv_bfloat16* __restrict__ A1h, const __nv_bfloat16* __restrict__ A1l,
                const __nv_bfloat16* __restrict__ B1h, const __nv_bfloat16* __restrict__ B1l,
                float* __restrict__ C1, const float* __restrict__ bias1) {
    extern __shared__ char sm[];
    const uint32_t smb = smem_to_u32(sm);
    const int tid  = threadIdx.x;
    const int wid  = tid >> 5;
    const int lane = tid & 31;

    const bool st1 = (blockIdx.y >= 16);
    const int  m0  = st1 ? (int)(blockIdx.y - 16) * 128 : (int)blockIdx.y * 128;
    const int  n0  = blockIdx.x * 64;
    const __nv_bfloat16* Ah = st1 ? A1h : A2h;
    const __nv_bfloat16* Al = st1 ? A1l : A2l;
    const __nv_bfloat16* Bh = st1 ? B1h : B2h;
    const __nv_bfloat16* Bl = st1 ? B1l : B2l;
    float* C = st1 ? C1 : C2;

    const int wm = (wid >> 2) * 64;        // warp m offset
    const int wn = (wid & 3) * 16;         // warp n offset

    float acc[4][2][4];
#pragma unroll
    for (int i = 0; i < 4; i++)
#pragma unroll
        for (int j = 0; j < 2; j++)
#pragma unroll
            for (int k = 0; k < 4; k++) acc[i][j][k] = 0.0f;

    // prologue: chunk 0
    cp_tileA(smb + OFF_AH, Ah, m0, 0, tid);
    cp_tileA(smb + OFF_AL, Al, m0, 0, tid);
    cp_tileB(smb + OFF_BH, Bh, n0, 0, tid);
    cp_tileB(smb + OFF_BL, Bl, n0, 0, tid);
    CP_COMMIT();

    const int lg = lane >> 3;              // 0..3
    const int lr = lane & 7;

    for (int c = 0; c < NC; c++) {
        if (c + 1 < NC) {
            uint32_t base = smb + ((c + 1) & 1) * STAGEB;
            const int kc = (c + 1) * BK;
            cp_tileA(base + OFF_AH, Ah, m0, kc, tid);
            cp_tileA(base + OFF_AL, Al, m0, kc, tid);
            cp_tileB(base + OFF_BH, Bh, n0, kc, tid);
            cp_tileB(base + OFF_BL, Bl, n0, kc, tid);
            CP_COMMIT();
            CP_WAIT1();
        } else {
            CP_WAIT0();
        }
        __syncthreads();

        const uint32_t base = smb + (c & 1) * STAGEB;

#pragma unroll
        for (int ks = 0; ks < 2; ks++) {
            const int k0 = ks * 16;
            uint32_t bH[2][2], bL[2][2];
            const uint32_t b_off =
                (uint32_t)((wn + ((lg >> 1) << 3) + lr) * ROWB + (k0 + ((lg & 1) << 3)) * 2);
            LDSM_X4(bH[0][0], bH[0][1], bH[1][0], bH[1][1], base + OFF_BH + b_off);
            LDSM_X4(bL[0][0], bL[0][1], bL[1][0], bL[1][1], base + OFF_BL + b_off);

            const uint32_t a_off =
                (uint32_t)((wm + ((lg & 1) << 3) + lr) * ROWB + (k0 + ((lg >> 1) << 3)) * 2);
#pragma unroll
            for (int mt = 0; mt < 4; mt++) {
                uint32_t aH[4], aL[4];
                LDSM_X4(aH[0], aH[1], aH[2], aH[3],
                        base + OFF_AH + a_off + mt * 16 * ROWB);
                LDSM_X4(aL[0], aL[1], aL[2], aL[3],
                        base + OFF_AL + a_off + mt * 16 * ROWB);
#pragma unroll
                for (int nt = 0; nt < 2; nt++) {
                    mma_bf16(acc[mt][nt], aH, bH[nt]);
                    mma_bf16(acc[mt][nt], aH, bL[nt]);
                    mma_bf16(acc[mt][nt], aL, bH[nt]);
                }
            }
        }
        __syncthreads();
    }

    // Epilogue
    const int row_base = m0 + wm + (lane >> 2);
    const int col_base = n0 + wn + (lane & 3) * 2;
#pragma unroll
    for (int mt = 0; mt < 4; mt++) {
#pragma unroll
        for (int nt = 0; nt < 2; nt++) {
            const int r = row_base + mt * 16;
            const int cc = col_base + nt * 8;
            float2 v01 = make_float2(acc[mt][nt][0], acc[mt][nt][1]);
            float2 v23 = make_float2(acc[mt][nt][2], acc[mt][nt][3]);
            if (st1) {
                float b0 = __ldg(&bias1[cc]);
                float b1 = __ldg(&bias1[cc + 1]);
                v01.x += b0; v01.y += b1;
                v23.x += b0; v23.y += b1;
            }
            *(float2*)&C[(size_t)r * Dq + cc] = v01;
            *(float2*)&C[(size_t)(r + 8) * Dq + cc] = v23;
        }
    }
}

// ---------------------------------------------------------------------------
// Fused attention epilogue, 8 frames per block, single wave (grid 256).
// rho inner loop uses tanh.approx.f16x2 (2 elements per MUFU op); args and
// accumulation stay fp32.
// ---------------------------------------------------------------------------
#define FPB 8
__global__ void __launch_bounds__(256, 2)
attn_kernel(const float* __restrict__ feat,
            const float* __restrict__ txt,
            const int*   __restrict__ qmask,
            const float* __restrict__ wv,
            const float* __restrict__ Wcw, const float* __restrict__ bcw,
            const float* __restrict__ Wcb, const float* __restrict__ bcb,
            float* __restrict__ out) {
    const int f0   = blockIdx.x * FPB;     // base bf index
    const int b    = f0 >> 8;              // F = 256
    const int tid  = threadIdx.x;
    const int warp = tid >> 5;
    const int lane = tid & 31;

    __shared__ float fp_s[FPB][Dq];        // 32 KB
    __shared__ float wv_s[Dq];             // 4 KB
    __shared__ float rho_s[FPB][Tq];
    __shared__ float red_s[2][FPB][8];
    __shared__ float scal_s[FPB][2];

    {
        const int i = tid * 4;
#pragma unroll
        for (int j = 0; j < FPB; j++)
            *(float4*)&fp_s[j][i] = *(const float4*)&g_fp[(size_t)(f0 + j) * Dq + i];
        *(float4*)&wv_s[i] = *(const float4*)&wv[i];
    }
    __syncthreads();

    // rho[j][t] = sum_d tanh(fp[j][d] + tpp[t][d]) * w[d]
    const float* tpp = g_tpp + (size_t)b * Tq * Dq;
    for (int t = warp; t < Tq; t += 8) {
        const float* tr = tpp + (size_t)t * Dq;
        float a[FPB];
#pragma unroll
        for (int j = 0; j < FPB; j++) a[j] = 0.0f;
#pragma unroll 2
        for (int d = lane * 4; d < Dq; d += 128) {
            float4 tv = *(const float4*)&tr[d];
            float4 w4 = *(const float4*)&wv_s[d];
#pragma unroll
            for (int j = 0; j < FPB; j++) {
                float4 f4 = *(const float4*)&fp_s[j][d];
                float2 t01 = tanh2_f16(f4.x + tv.x, f4.y + tv.y);
                float2 t23 = tanh2_f16(f4.z + tv.z, f4.w + tv.w);
                a[j] += t01.x * w4.x + t01.y * w4.y
                      + t23.x * w4.z + t23.y * w4.w;
            }
        }
#pragma unroll
        for (int o = 16; o; o >>= 1)
#pragma unroll
            for (int j = 0; j < FPB; j++)
                a[j] += __shfl_xor_sync(0xffffffffu, a[j], o);
        if (lane == 0) {
            float m = (float)qmask[b * Tq + t];
            float msk = (1.0f - m) * NEGV;
#pragma unroll
            for (int j = 0; j < FPB; j++)
                rho_s[j][t] = a[j] + msk;
        }
    }
    __syncthreads();

    // softmax over T=32 (warps 0..7, one frame each)
    {
        float v = rho_s[warp][lane];
        float mx = v;
#pragma unroll
        for (int o = 16; o; o >>= 1)
            mx = fmaxf(mx, __shfl_xor_sync(0xffffffffu, mx, o));
        float e = __expf(v - mx);
        float s = e;
#pragma unroll
        for (int o = 16; o; o >>= 1)
            s += __shfl_xor_sync(0xffffffffu, s, o);
        rho_s[warp][lane] = e / s;
    }
    __syncthreads();

    // txt_h[j] + two dot products
    const int d0 = tid * 4;
    float4 th[FPB];
#pragma unroll
    for (int j = 0; j < FPB; j++) th[j] = make_float4(0.f, 0.f, 0.f, 0.f);
    const float* tb = txt + (size_t)b * Tq * Dq + d0;
#pragma unroll 2
    for (int t = 0; t < Tq; t++) {
        float4 v = *(const float4*)(tb + (size_t)t * Dq);
#pragma unroll
        for (int j = 0; j < FPB; j++) {
            const float a = rho_s[j][t];
            th[j].x = fmaf(a, v.x, th[j].x);
            th[j].y = fmaf(a, v.y, th[j].y);
            th[j].z = fmaf(a, v.z, th[j].z);
            th[j].w = fmaf(a, v.w, th[j].w);
        }
    }
    float4 cw = *(const float4*)&Wcw[d0];
    float4 cb = *(const float4*)&Wcb[d0];
#pragma unroll
    for (int j = 0; j < FPB; j++) {
        float dw = th[j].x * cw.x + th[j].y * cw.y + th[j].z * cw.z + th[j].w * cw.w;
        float db = th[j].x * cb.x + th[j].y * cb.y + th[j].z * cb.z + th[j].w * cb.w;
#pragma unroll
        for (int o = 16; o; o >>= 1) {
            dw += __shfl_xor_sync(0xffffffffu, dw, o);
            db += __shfl_xor_sync(0xffffffffu, db, o);
        }
        if (lane == 0) {
            red_s[0][j][warp] = dw;
            red_s[1][j][warp] = db;
        }
    }
    __syncthreads();
    if (tid < FPB) {
        float sw = 0.f, sb = 0.f;
#pragma unroll
        for (int i = 0; i < 8; i++) {
            sw += red_s[0][tid][i];
            sb += red_s[1][tid][i];
        }
        scal_s[tid][0] = ftanh_fast(sw + bcw[0]);
        scal_s[tid][1] = ftanh_fast(sb + bcb[0]);
    }
    __syncthreads();

#pragma unroll
    for (int j = 0; j < FPB; j++) {
        const float ws = scal_s[j][0];
        const float bs = scal_s[j][1];
        float4 f = *(const float4*)&feat[(size_t)(f0 + j) * Dq + d0];
        float4 o4;
        o4.x = fmaf(ws, f.x, bs);
        o4.y = fmaf(ws, f.y, bs);
        o4.z = fmaf(ws, f.z, bs);
        o4.w = fmaf(ws, f.w, bs);
        *(float4*)&out[(size_t)(f0 + j) * Dq + d0] = o4;
    }
}

// ---------------------------------------------------------------------------
extern "C" void kernel_launch(void* const* d_in, const int* in_sizes, int n_in,
                              void* d_out, int out_size) {
    const float* features = (const float*)d_in[0];
    const float* txt      = (const float*)d_in[2];
    const int*   qm       = (const int*)  d_in[3];
    const float* Ws       = (const float*)d_in[4];
    const float* W        = (const float*)d_in[5];
    const float* wvec     = (const float*)d_in[6];
    const float* bvec     = (const float*)d_in[7];
    const float* Wcw      = (const float*)d_in[8];
    const float* bcw      = (const float*)d_in[9];
    const float* Wcb      = (const float*)d_in[10];
    const float* bcb      = (const float*)d_in[11];
    float* out = (float*)d_out;

    float *tpp_p, *fp_p;
    __nv_bfloat16 *fh, *fl, *th, *tl, *wth, *wtl, *wsh, *wsl;
    cudaGetSymbolAddress((void**)&tpp_p, g_tpp);
    cudaGetSymbolAddress((void**)&fp_p,  g_fp);
    cudaGetSymbolAddress((void**)&fh,  g_fh);
    cudaGetSymbolAddress((void**)&fl,  g_fl);
    cudaGetSymbolAddress((void**)&th,  g_th);
    cudaGetSymbolAddress((void**)&tl,  g_tl);
    cudaGetSymbolAddress((void**)&wth, g_wth);
    cudaGetSymbolAddress((void**)&wtl, g_wtl);
    cudaGetSymbolAddress((void**)&wsh, g_wsh);
    cudaGetSymbolAddress((void**)&wsl, g_wsl);

    cudaFuncSetAttribute(mma_gemm_kernel,
                         cudaFuncAttributeMaxDynamicSharedMemorySize, SMEM_GEMM);

    // 1) merged prep: activation split + weight transpose/split (one launch)
    prep_kernel<<<SPLIT_BLOCKS + TRANS_BLOCKS, 256>>>(
        features, fh, fl, txt, th, tl,
        W, wth, wtl, Ws, wsh, wsl);

    // 2) merged mma.sync GEMM, 288 CTAs, 2 CTAs/SM
    mma_gemm_kernel<<<dim3(Dq / 64, 18), 256, SMEM_GEMM>>>(
        fh, fl, wth, wtl, fp_p,
        th, tl, wsh, wsl, tpp_p, bvec);

    // 3) fused attention + film epilogue (256 blocks, one wave)
    attn_kernel<<<Bq * Fq / FPB, 256>>>(features, txt, qm, wvec,
                                        Wcw, bcw, Wcb, bcb, out);
}

// round 12
// speedup vs baseline: 1.0227x; 1.0198x over previous
#include <cuda_runtime.h>
#include <cuda_bf16.h>
#include <cstdint>

// Problem constants
#define Bq 8
#define Fq 256
#define Tq 32
#define Dq 1024
#define NEGV (-1e30f)

// ---------------------------------------------------------------------------
// Device-global scratch (no allocation allowed)
// ---------------------------------------------------------------------------
__device__ float g_tpp[Bq * Tq * Dq];            // txt@Ws + b     (1 MB)
__device__ float g_fp [Bq * Fq * Dq];            // feat@W         (8 MB)

__device__ __nv_bfloat16 g_fh [Bq * Fq * Dq];    // feat hi
__device__ __nv_bfloat16 g_fl [Bq * Fq * Dq];    // feat lo
__device__ __nv_bfloat16 g_th [Bq * Tq * Dq];    // txt hi
__device__ __nv_bfloat16 g_tl [Bq * Tq * Dq];    // txt lo
__device__ __nv_bfloat16 g_wth[Dq * Dq];         // W^T hi  ([n][k])
__device__ __nv_bfloat16 g_wtl[Dq * Dq];         // W^T lo
__device__ __nv_bfloat16 g_wsh[Dq * Dq];         // Ws^T hi
__device__ __nv_bfloat16 g_wsl[Dq * Dq];         // Ws^T lo

// ---------------------------------------------------------------------------
// Helpers
// ---------------------------------------------------------------------------
__device__ __forceinline__ uint32_t smem_to_u32(const void* p) {
    uint32_t a;
    asm("{ .reg .u64 t; cvta.to.shared.u64 t, %1; cvt.u32.u64 %0, t; }"
        : "=r"(a) : "l"(p));
    return a;
}

__device__ __forceinline__ void mma_bf16(float* c, const uint32_t* a, const uint32_t* b) {
    asm volatile(
        "mma.sync.aligned.m16n8k16.row.col.f32.bf16.bf16.f32 "
        "{%0,%1,%2,%3}, {%4,%5,%6,%7}, {%8,%9}, {%0,%1,%2,%3};"
        : "+f"(c[0]), "+f"(c[1]), "+f"(c[2]), "+f"(c[3])
        : "r"(a[0]), "r"(a[1]), "r"(a[2]), "r"(a[3]), "r"(b[0]), "r"(b[1]));
}

#define LDSM_X4(r0, r1, r2, r3, addr)                                        \
    asm volatile("ldmatrix.sync.aligned.m8n8.x4.shared.b16 {%0,%1,%2,%3}, [%4];" \
                 : "=r"(r0), "=r"(r1), "=r"(r2), "=r"(r3) : "r"(addr))

__device__ __forceinline__ void cp16(uint32_t dst, const void* src) {
    asm volatile("cp.async.cg.shared.global [%0], [%1], 16;" :: "r"(dst), "l"(src));
}
#define CP_COMMIT() asm volatile("cp.async.commit_group;" ::: "memory")
#define CP_WAIT1()  asm volatile("cp.async.wait_group 1;" ::: "memory")
#define CP_WAIT0()  asm volatile("cp.async.wait_group 0;" ::: "memory")

// single-MUFU tanh (fp32 — restored; f16x2 variant measured neutral w/ 50x err)
__device__ __forceinline__ float tanh_mufu(float x) {
    float y;
    asm("tanh.approx.f32 %0, %1;" : "=f"(y) : "f"(x));
    return y;
}
// 2-MUFU accurate tanh (for the per-block film scalars)
__device__ __forceinline__ float ftanh_fast(float x) {
    float e = __expf(2.0f * x);
    return 1.0f - __fdividef(2.0f, e + 1.0f);
}

// ---------------------------------------------------------------------------
// Merged prep: activation hi/lo split + weight transpose/split in ONE launch.
// ---------------------------------------------------------------------------
#define FEAT4 (Bq * Fq * Dq / 4)
#define TXT4  (Bq * Tq * Dq / 4)
#define SPLIT_BLOCKS ((FEAT4 + TXT4 + 255) / 256)   // 2304
#define TRANS_BLOCKS (32 * 32 * 2)                  // 2048

__global__ void __launch_bounds__(256)
prep_kernel(const float* __restrict__ feat, __nv_bfloat16* __restrict__ fh,
            __nv_bfloat16* __restrict__ fl,
            const float* __restrict__ txt, __nv_bfloat16* __restrict__ th,
            __nv_bfloat16* __restrict__ tl,
            const float* __restrict__ W0, __nv_bfloat16* __restrict__ H0,
            __nv_bfloat16* __restrict__ L0,
            const float* __restrict__ W1, __nv_bfloat16* __restrict__ H1,
            __nv_bfloat16* __restrict__ L1) {
    __shared__ float ts[32][33];
    const int blk = blockIdx.x;
    const int tid = threadIdx.x;

    if (blk < SPLIT_BLOCKS) {
        int i = blk * 256 + tid;
        const float* in;
        __nv_bfloat16 *hi, *lo;
        if (i < FEAT4) {
            in = feat; hi = fh; lo = fl;
        } else if (i < FEAT4 + TXT4) {
            i -= FEAT4;
            in = txt; hi = th; lo = tl;
        } else {
            return;
        }
        float4 v = ((const float4*)in)[i];
        __nv_bfloat16 h0 = __float2bfloat16(v.x);
        __nv_bfloat16 h1 = __float2bfloat16(v.y);
        __nv_bfloat16 h2 = __float2bfloat16(v.z);
        __nv_bfloat16 h3 = __float2bfloat16(v.w);
        __nv_bfloat16 l0 = __float2bfloat16(v.x - __bfloat162float(h0));
        __nv_bfloat16 l1 = __float2bfloat16(v.y - __bfloat162float(h1));
        __nv_bfloat16 l2 = __float2bfloat16(v.z - __bfloat162float(h2));
        __nv_bfloat16 l3 = __float2bfloat16(v.w - __bfloat162float(h3));
        ((__nv_bfloat162*)hi)[2 * i]     = __nv_bfloat162(h0, h1);
        ((__nv_bfloat162*)hi)[2 * i + 1] = __nv_bfloat162(h2, h3);
        ((__nv_bfloat162*)lo)[2 * i]     = __nv_bfloat162(l0, l1);
        ((__nv_bfloat162*)lo)[2 * i + 1] = __nv_bfloat162(l2, l3);
    } else {
        const int idx   = blk - SPLIT_BLOCKS;
        const int which = idx >> 10;            // 0 -> W, 1 -> Ws
        const int tile  = idx & 1023;
        const int n0 = (tile & 31) * 32;
        const int k0 = (tile >> 5) * 32;
        const float* in = which ? W1 : W0;
        __nv_bfloat16* hi = which ? H1 : H0;
        __nv_bfloat16* lo = which ? L1 : L0;
        const int tx = tid & 31, ty = tid >> 5;  // (32, 8)
#pragma unroll
        for (int i = 0; i < 32; i += 8)
            ts[ty + i][tx] = in[(size_t)(k0 + ty + i) * Dq + n0 + tx];
        __syncthreads();
#pragma unroll
        for (int i = 0; i < 32; i += 8) {
            float v = ts[tx][ty + i];           // = W[k0+tx][n0+ty+i]
            __nv_bfloat16 h = __float2bfloat16(v);
            __nv_bfloat16 l = __float2bfloat16(v - __bfloat162float(h));
            size_t o = (size_t)(n0 + ty + i) * Dq + k0 + tx;
            hi[o] = h;
            lo[o] = l;
        }
    }
}

// ---------------------------------------------------------------------------
// bf16x3 emulated-fp32 GEMM on mma.sync (m16n8k16 bf16).
// CTA tile 128(m) x 64(n), BK=32, 2-stage cp.async pipeline, 2 CTAs/SM.
// Launched with PDL: blocks start during prep's tail; griddepsync gates the
// first read of prep outputs.
// ---------------------------------------------------------------------------
#define BK 32
#define NC (Dq / BK)                 // 32
#define ROWB 80                      // 32 bf16 = 64B + 16B pad (conflict-free)
#define ATILE (128 * ROWB)           // 10240
#define BTILE (64 * ROWB)            // 5120
#define OFF_AH 0
#define OFF_AL ATILE
#define OFF_BH (2 * ATILE)
#define OFF_BL (2 * ATILE + BTILE)
#define STAGEB (2 * ATILE + 2 * BTILE)   // 30720
#define SMEM_GEMM (2 * STAGEB)           // 61440

__device__ __forceinline__ void cp_tileA(uint32_t s, const __nv_bfloat16* __restrict__ g,
                                         int row0, int kc, int tid) {
#pragma unroll
    for (int i = 0; i < 2; i++) {
        int idx = tid + (i << 8);          // 0..511
        int r = idx >> 2, c = idx & 3;
        cp16(s + r * ROWB + c * 16, g + (size_t)(row0 + r) * Dq + kc + c * 8);
    }
}
__device__ __forceinline__ void cp_tileB(uint32_t s, const __nv_bfloat16* __restrict__ g,
                                         int row0, int kc, int tid) {
    int r = tid >> 2, c = tid & 3;         // 64 rows x 4 chunks
    cp16(s + r * ROWB + c * 16, g + (size_t)(row0 + r) * Dq + kc + c * 8);
}

__global__ void __launch_bounds__(256, 2)
mma_gemm_kernel(const __nv_bfloat16* __restrict__ A2h, const __nv_bfloat16* __restrict__ A2l,
                const __nv_bfloat16* __restrict__ B2h, const __nv_bfloat16* __restrict__ B2l,
                float* __restrict__ C2,
                const __nv_bfloat16* __restrict__ A1h, const __nv_bfloat16* __restrict__ A1l,
                const __nv_bfloat16* __restrict__ B1h, const __nv_bfloat16* __restrict__ B1l,
                float* __restrict__ C1, const float* __restrict__ bias1) {
    extern __shared__ char sm[];
    const uint32_t smb = smem_to_u32(sm);
    const int tid  = threadIdx.x;
    const int wid  = tid >> 5;
    const int lane = tid & 31;

    const bool st1 = (blockIdx.y >= 16);
    const int  m0  = st1 ? (int)(blockIdx.y - 16) * 128 : (int)blockIdx.y * 128;
    const int  n0  = blockIdx.x * 64;
    const __nv_bfloat16* Ah = st1 ? A1h : A2h;
    const __nv_bfloat16* Al = st1 ? A1l : A2l;
    const __nv_bfloat16* Bh = st1 ? B1h : B2h;
    const __nv_bfloat16* Bl = st1 ? B1l : B2l;
    float* C = st1 ? C1 : C2;

    const int wm = (wid >> 2) * 64;        // warp m offset
    const int wn = (wid & 3) * 16;         // warp n offset

    float acc[4][2][4];
#pragma unroll
    for (int i = 0; i < 4; i++)
#pragma unroll
        for (int j = 0; j < 2; j++)
#pragma unroll
            for (int k = 0; k < 4; k++) acc[i][j][k] = 0.0f;

    // PDL: wait for prep to fully commit its outputs before first read.
    cudaGridDependencySynchronize();

    // prologue: chunk 0
    cp_tileA(smb + OFF_AH, Ah, m0, 0, tid);
    cp_tileA(smb + OFF_AL, Al, m0, 0, tid);
    cp_tileB(smb + OFF_BH, Bh, n0, 0, tid);
    cp_tileB(smb + OFF_BL, Bl, n0, 0, tid);
    CP_COMMIT();

    const int lg = lane >> 3;              // 0..3
    const int lr = lane & 7;

    for (int c = 0; c < NC; c++) {
        if (c + 1 < NC) {
            uint32_t base = smb + ((c + 1) & 1) * STAGEB;
            const int kc = (c + 1) * BK;
            cp_tileA(base + OFF_AH, Ah, m0, kc, tid);
            cp_tileA(base + OFF_AL, Al, m0, kc, tid);
            cp_tileB(base + OFF_BH, Bh, n0, kc, tid);
            cp_tileB(base + OFF_BL, Bl, n0, kc, tid);
            CP_COMMIT();
            CP_WAIT1();
        } else {
            CP_WAIT0();
        }
        __syncthreads();

        const uint32_t base = smb + (c & 1) * STAGEB;

#pragma unroll
        for (int ks = 0; ks < 2; ks++) {
            const int k0 = ks * 16;
            uint32_t bH[2][2], bL[2][2];
            const uint32_t b_off =
                (uint32_t)((wn + ((lg >> 1) << 3) + lr) * ROWB + (k0 + ((lg & 1) << 3)) * 2);
            LDSM_X4(bH[0][0], bH[0][1], bH[1][0], bH[1][1], base + OFF_BH + b_off);
            LDSM_X4(bL[0][0], bL[0][1], bL[1][0], bL[1][1], base + OFF_BL + b_off);

            const uint32_t a_off =
                (uint32_t)((wm + ((lg & 1) << 3) + lr) * ROWB + (k0 + ((lg >> 1) << 3)) * 2);
#pragma unroll
            for (int mt = 0; mt < 4; mt++) {
                uint32_t aH[4], aL[4];
                LDSM_X4(aH[0], aH[1], aH[2], aH[3],
                        base + OFF_AH + a_off + mt * 16 * ROWB);
                LDSM_X4(aL[0], aL[1], aL[2], aL[3],
                        base + OFF_AL + a_off + mt * 16 * ROWB);
#pragma unroll
                for (int nt = 0; nt < 2; nt++) {
                    mma_bf16(acc[mt][nt], aH, bH[nt]);
                    mma_bf16(acc[mt][nt], aH, bL[nt]);
                    mma_bf16(acc[mt][nt], aL, bH[nt]);
                }
            }
        }
        __syncthreads();
    }

    // Epilogue
    const int row_base = m0 + wm + (lane >> 2);
    const int col_base = n0 + wn + (lane & 3) * 2;
#pragma unroll
    for (int mt = 0; mt < 4; mt++) {
#pragma unroll
        for (int nt = 0; nt < 2; nt++) {
            const int r = row_base + mt * 16;
            const int cc = col_base + nt * 8;
            float2 v01 = make_float2(acc[mt][nt][0], acc[mt][nt][1]);
            float2 v23 = make_float2(acc[mt][nt][2], acc[mt][nt][3]);
            if (st1) {
                float b0 = __ldg(&bias1[cc]);
                float b1 = __ldg(&bias1[cc + 1]);
                v01.x += b0; v01.y += b1;
                v23.x += b0; v23.y += b1;
            }
            *(float2*)&C[(size_t)r * Dq + cc] = v01;
            *(float2*)&C[(size_t)(r + 8) * Dq + cc] = v23;
        }
    }
}

// ---------------------------------------------------------------------------
// Fused attention epilogue, 8 frames per block, single wave (grid 256).
// fp32 tanh (R9-exact). Launched with PDL: blocks start during GEMM's tail;
// griddepsync gates the first read of g_fp / g_tpp.
// ---------------------------------------------------------------------------
#define FPB 8
__global__ void __launch_bounds__(256, 2)
attn_kernel(const float* __restrict__ feat,
            const float* __restrict__ txt,
            const int*   __restrict__ qmask,
            const float* __restrict__ wv,
            const float* __restrict__ Wcw, const float* __restrict__ bcw,
            const float* __restrict__ Wcb, const float* __restrict__ bcb,
            float* __restrict__ out) {
    const int f0   = blockIdx.x * FPB;     // base bf index
    const int b    = f0 >> 8;              // F = 256
    const int tid  = threadIdx.x;
    const int warp = tid >> 5;
    const int lane = tid & 31;

    __shared__ float fp_s[FPB][Dq];        // 32 KB
    __shared__ float wv_s[Dq];             // 4 KB
    __shared__ float rho_s[FPB][Tq];
    __shared__ float red_s[2][FPB][8];
    __shared__ float scal_s[FPB][2];

    // PDL: wait for the GEMM grid to finish before consuming g_fp / g_tpp.
    cudaGridDependencySynchronize();

    {
        const int i = tid * 4;
#pragma unroll
        for (int j = 0; j < FPB; j++)
            *(float4*)&fp_s[j][i] = *(const float4*)&g_fp[(size_t)(f0 + j) * Dq + i];
        *(float4*)&wv_s[i] = *(const float4*)&wv[i];
    }
    __syncthreads();

    // rho[j][t] = sum_d tanh(fp[j][d] + tpp[t][d]) * w[d]
    const float* tpp = g_tpp + (size_t)b * Tq * Dq;
    for (int t = warp; t < Tq; t += 8) {
        const float* tr = tpp + (size_t)t * Dq;
        float a[FPB];
#pragma unroll
        for (int j = 0; j < FPB; j++) a[j] = 0.0f;
#pragma unroll 2
        for (int d = lane * 4; d < Dq; d += 128) {
            float4 tv = *(const float4*)&tr[d];
            float4 w4 = *(const float4*)&wv_s[d];
#pragma unroll
            for (int j = 0; j < FPB; j++) {
                float4 f4 = *(const float4*)&fp_s[j][d];
                a[j] += tanh_mufu(f4.x + tv.x) * w4.x + tanh_mufu(f4.y + tv.y) * w4.y
                      + tanh_mufu(f4.z + tv.z) * w4.z + tanh_mufu(f4.w + tv.w) * w4.w;
            }
        }
#pragma unroll
        for (int o = 16; o; o >>= 1)
#pragma unroll
            for (int j = 0; j < FPB; j++)
                a[j] += __shfl_xor_sync(0xffffffffu, a[j], o);
        if (lane == 0) {
            float m = (float)qmask[b * Tq + t];
            float msk = (1.0f - m) * NEGV;
#pragma unroll
            for (int j = 0; j < FPB; j++)
                rho_s[j][t] = a[j] + msk;
        }
    }
    __syncthreads();

    // softmax over T=32 (warps 0..7, one frame each)
    {
        float v = rho_s[warp][lane];
        float mx = v;
#pragma unroll
        for (int o = 16; o; o >>= 1)
            mx = fmaxf(mx, __shfl_xor_sync(0xffffffffu, mx, o));
        float e = __expf(v - mx);
        float s = e;
#pragma unroll
        for (int o = 16; o; o >>= 1)
            s += __shfl_xor_sync(0xffffffffu, s, o);
        rho_s[warp][lane] = e / s;
    }
    __syncthreads();

    // txt_h[j] + two dot products
    const int d0 = tid * 4;
    float4 th[FPB];
#pragma unroll
    for (int j = 0; j < FPB; j++) th[j] = make_float4(0.f, 0.f, 0.f, 0.f);
    const float* tb = txt + (size_t)b * Tq * Dq + d0;
#pragma unroll 2
    for (int t = 0; t < Tq; t++) {
        float4 v = *(const float4*)(tb + (size_t)t * Dq);
#pragma unroll
        for (int j = 0; j < FPB; j++) {
            const float a = rho_s[j][t];
            th[j].x = fmaf(a, v.x, th[j].x);
            th[j].y = fmaf(a, v.y, th[j].y);
            th[j].z = fmaf(a, v.z, th[j].z);
            th[j].w = fmaf(a, v.w, th[j].w);
        }
    }
    float4 cw = *(const float4*)&Wcw[d0];
    float4 cb = *(const float4*)&Wcb[d0];
#pragma unroll
    for (int j = 0; j < FPB; j++) {
        float dw = th[j].x * cw.x + th[j].y * cw.y + th[j].z * cw.z + th[j].w * cw.w;
        float db = th[j].x * cb.x + th[j].y * cb.y + th[j].z * cb.z + th[j].w * cb.w;
#pragma unroll
        for (int o = 16; o; o >>= 1) {
            dw += __shfl_xor_sync(0xffffffffu, dw, o);
            db += __shfl_xor_sync(0xffffffffu, db, o);
        }
        if (lane == 0) {
            red_s[0][j][warp] = dw;
            red_s[1][j][warp] = db;
        }
    }
    __syncthreads();
    if (tid < FPB) {
        float sw = 0.f, sb = 0.f;
#pragma unroll
        for (int i = 0; i < 8; i++) {
            sw += red_s[0][tid][i];
            sb += red_s[1][tid][i];
        }
        scal_s[tid][0] = ftanh_fast(sw + bcw[0]);
        scal_s[tid][1] = ftanh_fast(sb + bcb[0]);
    }
    __syncthreads();

#pragma unroll
    for (int j = 0; j < FPB; j++) {
        const float ws = scal_s[j][0];
        const float bs = scal_s[j][1];
        float4 f = *(const float4*)&feat[(size_t)(f0 + j) * Dq + d0];
        float4 o4;
        o4.x = fmaf(ws, f.x, bs);
        o4.y = fmaf(ws, f.y, bs);
        o4.z = fmaf(ws, f.z, bs);
        o4.w = fmaf(ws, f.w, bs);
        *(float4*)&out[(size_t)(f0 + j) * Dq + d0] = o4;
    }
}

// ---------------------------------------------------------------------------
extern "C" void kernel_launch(void* const* d_in, const int* in_sizes, int n_in,
                              void* d_out, int out_size) {
    const float* features = (const float*)d_in[0];
    const float* txt      = (const float*)d_in[2];
    const int*   qm       = (const int*)  d_in[3];
    const float* Ws       = (const float*)d_in[4];
    const float* W        = (const float*)d_in[5];
    const float* wvec     = (const float*)d_in[6];
    const float* bvec     = (const float*)d_in[7];
    const float* Wcw      = (const float*)d_in[8];
    const float* bcw      = (const float*)d_in[9];
    const float* Wcb      = (const float*)d_in[10];
    const float* bcb      = (const float*)d_in[11];
    float* out = (float*)d_out;

    float *tpp_p, *fp_p;
    __nv_bfloat16 *fh, *fl, *th, *tl, *wth, *wtl, *wsh, *wsl;
    cudaGetSymbolAddress((void**)&tpp_p, g_tpp);
    cudaGetSymbolAddress((void**)&fp_p,  g_fp);
    cudaGetSymbolAddress((void**)&fh,  g_fh);
    cudaGetSymbolAddress((void**)&fl,  g_fl);
    cudaGetSymbolAddress((void**)&th,  g_th);
    cudaGetSymbolAddress((void**)&tl,  g_tl);
    cudaGetSymbolAddress((void**)&wth, g_wth);
    cudaGetSymbolAddress((void**)&wtl, g_wtl);
    cudaGetSymbolAddress((void**)&wsh, g_wsh);
    cudaGetSymbolAddress((void**)&wsl, g_wsl);

    cudaFuncSetAttribute(mma_gemm_kernel,
                         cudaFuncAttributeMaxDynamicSharedMemorySize, SMEM_GEMM);

    // 1) merged prep: activation split + weight transpose/split (one launch)
    prep_kernel<<<SPLIT_BLOCKS + TRANS_BLOCKS, 256>>>(
        features, fh, fl, txt, th, tl,
        W, wth, wtl, Ws, wsh, wsl);

    // PDL attribute: secondary may launch while primary drains; consumer
    // kernels call cudaGridDependencySynchronize() before touching producer
    // outputs.
    cudaLaunchAttribute pdl[1];
    pdl[0].id = cudaLaunchAttributeProgrammaticStreamSerialization;
    pdl[0].val.programmaticStreamSerializationAllowed = 1;

    // 2) merged mma.sync GEMM, 288 CTAs, 2 CTAs/SM — PDL-overlapped with prep
    {
        cudaLaunchConfig_t cfg = {};
        cfg.gridDim = dim3(Dq / 64, 18);
        cfg.blockDim = dim3(256);
        cfg.dynamicSmemBytes = SMEM_GEMM;
        cfg.stream = 0;
        cfg.attrs = pdl;
        cfg.numAttrs = 1;
        cudaLaunchKernelEx(&cfg, mma_gemm_kernel,
                           (const __nv_bfloat16*)fh, (const __nv_bfloat16*)fl,
                           (const __nv_bfloat16*)wth, (const __nv_bfloat16*)wtl,
                           fp_p,
                           (const __nv_bfloat16*)th, (const __nv_bfloat16*)tl,
                           (const __nv_bfloat16*)wsh, (const __nv_bfloat16*)wsl,
                           tpp_p, bvec);
    }

    // 3) fused attention + film epilogue — PDL-overlapped with GEMM tail
    {
        cudaLaunchConfig_t cfg = {};
        cfg.gridDim = dim3(Bq * Fq / FPB);
        cfg.blockDim = dim3(256);
        cfg.dynamicSmemBytes = 0;
        cfg.stream = 0;
        cfg.attrs = pdl;
        cfg.numAttrs = 1;
        cudaLaunchKernelEx(&cfg, attn_kernel,
                           features, txt, qm, wvec,
                           Wcw, bcw, Wcb, bcb, out);
    }
}